// round 6
// baseline (speedup 1.0000x reference)
#include <cuda_runtime.h>
#include <cuda_fp16.h>
#include <mma.h>
#include <cstdint>

using namespace nvcuda;

#define NMAX 30000

// ---------------- scratch (no allocation allowed) ----------------
__device__ __half g_featH[NMAX * 128];     // fp16 copy of input feats
__device__ __half g_w0h[3 * 128 * 256];    // fp16 W0
__device__ __half g_w1h[3 * 256 * 256];    // fp16 W1
__device__ __half g_h [NMAX * 768];        // projected feats fp16, [N][t][256]
__device__ __half g_x1h[NMAX * 256];       // layer-0 output (fp16)
__device__ __half g_x2h[NMAX * 256];       // layer-1 output (fp16)
__device__ float  g_el[NMAX * 12];         // [N][t][head]
__device__ float  g_er[NMAX * 12];
__device__ float  g_h2[NMAX * 6];          // layer-2 projected [N][t][2]

// ---------------- fused fp32 -> fp16 conversion (3 segments) ----------------
__global__ __launch_bounds__(256) void f2h_all(
    const float* __restrict__ in0, __half* __restrict__ out0, int n0,
    const float* __restrict__ in1, __half* __restrict__ out1, int n1,
    const float* __restrict__ in2, __half* __restrict__ out2, int n2)
{
    int i = blockIdx.x * blockDim.x + threadIdx.x;   // float4 index
    const float* in; __half* out;
    if (i < n0)            { in = in0; out = out0; }
    else if ((i -= n0) < n1) { in = in1; out = out1; }
    else if ((i -= n1) < n2) { in = in2; out = out2; }
    else return;
    float4 v = reinterpret_cast<const float4*>(in)[i];
    __half2 a = __floats2half2_rn(v.x, v.y);
    __half2 b = __floats2half2_rn(v.z, v.w);
    reinterpret_cast<__half2*>(out)[2 * i + 0] = a;
    reinterpret_cast<__half2*>(out)[2 * i + 1] = b;
}

// ---------------- HMMA GEMM: C_fp16[N,768] = X_fp16[N,K] @ {W_t_fp16[K,256]} ----
#define BM 128
#define BN 128
#define BKH 32
#define APAD 16
#define BPAD 16

__global__ __launch_bounds__(256, 2) void hgemm(
    const __half* __restrict__ X, const __half* __restrict__ W,
    __half* __restrict__ C, int M, int K)
{
    __shared__ __half As[BM][BKH + APAD];
    __shared__ __half Bs[BKH][BN + BPAD];

    const int tid  = threadIdx.x;
    const int wid  = tid >> 5;
    const int lane = tid & 31;
    const int row0 = blockIdx.x * BM;
    const int ct   = blockIdx.y;
    const int t    = ct >> 1;
    const int colbase = (ct & 1) * 128;
    const __half* Wt = W + (size_t)t * K * 256;

    const int wm = wid >> 1;
    const int wn = wid & 1;

    wmma::fragment<wmma::accumulator, 16, 16, 16, float> acc[2][4];
    #pragma unroll
    for (int i = 0; i < 2; i++)
        #pragma unroll
        for (int j = 0; j < 4; j++) wmma::fill_fragment(acc[i][j], 0.0f);

    const int ar = tid >> 1;
    const int as = (tid & 1) * 16;
    const int br = tid >> 3;
    const int bs = (tid & 7) * 16;

    for (int k0 = 0; k0 < K; k0 += BKH) {
        uint4 v0 = make_uint4(0u, 0u, 0u, 0u), v1 = v0;
        if (row0 + ar < M) {
            const __half* xp = X + (size_t)(row0 + ar) * K + k0 + as;
            v0 = *reinterpret_cast<const uint4*>(xp);
            v1 = *reinterpret_cast<const uint4*>(xp + 8);
        }
        *reinterpret_cast<uint4*>(&As[ar][as])     = v0;
        *reinterpret_cast<uint4*>(&As[ar][as + 8]) = v1;

        const __half* wp = Wt + (size_t)(k0 + br) * 256 + colbase + bs;
        *reinterpret_cast<uint4*>(&Bs[br][bs])     = *reinterpret_cast<const uint4*>(wp);
        *reinterpret_cast<uint4*>(&Bs[br][bs + 8]) = *reinterpret_cast<const uint4*>(wp + 8);

        __syncthreads();

        #pragma unroll
        for (int kk = 0; kk < BKH; kk += 16) {
            wmma::fragment<wmma::matrix_a, 16, 16, 16, __half, wmma::row_major> af[2];
            wmma::fragment<wmma::matrix_b, 16, 16, 16, __half, wmma::row_major> bf[4];
            #pragma unroll
            for (int i = 0; i < 2; i++)
                wmma::load_matrix_sync(af[i], &As[wm * 32 + i * 16][kk], BKH + APAD);
            #pragma unroll
            for (int j = 0; j < 4; j++)
                wmma::load_matrix_sync(bf[j], &Bs[kk][wn * 64 + j * 16], BN + BPAD);
            #pragma unroll
            for (int i = 0; i < 2; i++)
                #pragma unroll
                for (int j = 0; j < 4; j++)
                    wmma::mma_sync(acc[i][j], af[i], bf[j], acc[i][j]);
        }
        __syncthreads();
    }

    float* patch = reinterpret_cast<float*>(&As[0][0]) + wid * 256;
    const int pr = lane >> 1;
    const int pc = (lane & 1) * 8;

    #pragma unroll
    for (int i = 0; i < 2; i++) {
        #pragma unroll
        for (int j = 0; j < 4; j++) {
            wmma::store_matrix_sync(patch, acc[i][j], 16, wmma::mem_row_major);
            __syncwarp();
            const int grow = row0 + wm * 32 + i * 16 + pr;
            if (grow < M) {
                __half2 hv[4];
                #pragma unroll
                for (int q = 0; q < 4; q++)
                    hv[q] = __floats2half2_rn(patch[pr * 16 + pc + 2 * q],
                                              patch[pr * 16 + pc + 2 * q + 1]);
                *reinterpret_cast<uint4*>(
                    C + (size_t)grow * 768 + ct * 128 + wn * 64 + j * 16 + pc) =
                    *reinterpret_cast<uint4*>(hv);
            }
            __syncwarp();
        }
    }
}

// ---------------- el/er: warp per (node, etype), vectorized ----------------
__global__ __launch_bounds__(256) void eler_kernel(
    const __half* __restrict__ h, const float* __restrict__ al,
    const float* __restrict__ ar, float* __restrict__ el,
    float* __restrict__ er, int n)
{
    const int w    = (blockIdx.x * blockDim.x + threadIdx.x) >> 5;
    const int lane = threadIdx.x & 31;
    if (w >= n * 3) return;
    const int i = w / 3, t = w % 3;

    // lane covers cols [lane*8, lane*8+8) -> single head = lane>>3
    const __half* hp = h + (size_t)i * 768 + t * 256 + lane * 8;
    uint4 v = *reinterpret_cast<const uint4*>(hp);
    const __half2* hv = reinterpret_cast<const __half2*>(&v);

    float se = 0.f, sr = 0.f;
    #pragma unroll
    for (int q = 0; q < 4; q++) {
        float2 f = __half22float2(hv[q]);
        const int d = t * 256 + lane * 8 + 2 * q;
        se += f.x * al[d] + f.y * al[d + 1];
        sr += f.x * ar[d] + f.y * ar[d + 1];
    }
    // reduce within 8-lane head group
    #pragma unroll
    for (int o = 1; o < 8; o <<= 1) {
        se += __shfl_xor_sync(0xffffffffu, se, o);
        sr += __shfl_xor_sync(0xffffffffu, sr, o);
    }
    if ((lane & 7) == 0) {
        const int head = lane >> 3;
        el[(size_t)i * 12 + t * 4 + head] = se;
        er[(size_t)i * 12 + t * 4 + head] = sr;
    }
}

// ---------------- aggregation: block per node, vectorized gathers ----------
__global__ __launch_bounds__(128) void agg_kernel(
    const __half* __restrict__ h, const float* __restrict__ el,
    const float* __restrict__ er, const int* __restrict__ src,
    const float* __restrict__ bias, __half* __restrict__ xout,
    int n)
{
    const int i   = blockIdx.x;
    const int tid = threadIdx.x;
    const int E   = n * 16;

    __shared__ int   s_src[48];
    __shared__ float s_alpha[12][16];     // [t*4+head][j]
    __shared__ float s_part[3][256];

    if (tid < 48) {
        const int t = tid >> 4, j = tid & 15;
        s_src[tid] = src[(size_t)t * E + i * 16 + j];
    }
    __syncthreads();

    if (tid < 12) {
        const int t = tid >> 2;
        const float eri = er[(size_t)i * 12 + tid];
        float e[16];
        float mx = -1e30f;
        #pragma unroll
        for (int j = 0; j < 16; j++) {
            const int s = s_src[t * 16 + j];
            float v = el[(size_t)s * 12 + tid] + eri;
            v = v > 0.f ? v : 0.2f * v;
            e[j] = v;
            mx = fmaxf(mx, v);
        }
        float sum = 0.f;
        #pragma unroll
        for (int j = 0; j < 16; j++) { e[j] = __expf(e[j] - mx); sum += e[j]; }
        const float inv = 1.0f / sum;
        #pragma unroll
        for (int j = 0; j < 16; j++) s_alpha[tid][j] = e[j] * inv;
    }
    __syncthreads();

    // 96 threads: warp t handles etype t; lane = col octet (8 halfs, 16B loads)
    if (tid < 96) {
        const int t   = tid >> 5;
        const int oct = tid & 31;
        const int head = oct >> 3;
        const float* ap = s_alpha[t * 4 + head];
        const __half* hb = h + t * 256 + oct * 8;

        float acc[8] = {0.f, 0.f, 0.f, 0.f, 0.f, 0.f, 0.f, 0.f};
        #pragma unroll
        for (int j = 0; j < 16; j++) {
            const float a = ap[j];
            uint4 v = *reinterpret_cast<const uint4*>(
                hb + (size_t)s_src[t * 16 + j] * 768);
            const __half2* hv = reinterpret_cast<const __half2*>(&v);
            #pragma unroll
            for (int q = 0; q < 4; q++) {
                float2 f = __half22float2(hv[q]);
                acc[2 * q]     += a * f.x;
                acc[2 * q + 1] += a * f.y;
            }
        }
        #pragma unroll
        for (int q = 0; q < 8; q++) s_part[t][oct * 8 + q] = acc[q];
    }
    __syncthreads();

    // 32 threads: combine etypes, bias, mean, ELU, fp16 vector store
    if (tid < 32) {
        const int oct = tid;
        __half2 hv[4];
        #pragma unroll
        for (int q = 0; q < 4; q++) {
            float r[2];
            #pragma unroll
            for (int u = 0; u < 2; u++) {
                const int c = oct * 8 + 2 * q + u;
                float s = s_part[0][c] + s_part[1][c] + s_part[2][c]
                        + bias[c] + bias[256 + c] + bias[512 + c];
                s *= (1.0f / 3.0f);
                r[u] = s > 0.f ? s : (__expf(s) - 1.0f);
            }
            hv[q] = __floats2half2_rn(r[0], r[1]);
        }
        *reinterpret_cast<uint4*>(xout + (size_t)i * 256 + oct * 8) =
            *reinterpret_cast<uint4*>(hv);
    }
}

// ---------------- layer-2 projection: warp per row, vectorized -------------
__global__ __launch_bounds__(256) void gemm2_kernel(
    const __half* __restrict__ X, const float* __restrict__ W2,
    float* __restrict__ h2, int n)
{
    const int w    = (blockIdx.x * blockDim.x + threadIdx.x) >> 5;
    const int lane = threadIdx.x & 31;
    if (w >= n) return;

    uint4 v = *reinterpret_cast<const uint4*>(X + (size_t)w * 256 + lane * 8);
    const __half2* hv = reinterpret_cast<const __half2*>(&v);

    float s[6] = {0.f, 0.f, 0.f, 0.f, 0.f, 0.f};
    #pragma unroll
    for (int q = 0; q < 4; q++) {
        float2 f = __half22float2(hv[q]);
        const int d = lane * 8 + 2 * q;
        #pragma unroll
        for (int t = 0; t < 3; t++) {
            s[t * 2 + 0] += f.x * W2[t * 512 + d * 2 + 0] + f.y * W2[t * 512 + (d + 1) * 2 + 0];
            s[t * 2 + 1] += f.x * W2[t * 512 + d * 2 + 1] + f.y * W2[t * 512 + (d + 1) * 2 + 1];
        }
    }
    #pragma unroll
    for (int o = 16; o > 0; o >>= 1)
        #pragma unroll
        for (int q = 0; q < 6; q++)
            s[q] += __shfl_xor_sync(0xffffffffu, s[q], o);
    if (lane < 6) h2[(size_t)w * 6 + lane] = s[lane];
}

// ---------------- final: layer-2 attention + outputs ----------------
__global__ __launch_bounds__(128) void final_kernel(
    const float* __restrict__ h2, const float* __restrict__ al2,
    const float* __restrict__ ar2, const float* __restrict__ b2,
    const int* __restrict__ src, float* __restrict__ out,
    int n, int out_size)
{
    const int i = blockIdx.x * blockDim.x + threadIdx.x;
    if (i >= n) return;
    const int E = n * 16;

    float acc0 = 0.f, acc1 = 0.f;
    for (int t = 0; t < 3; t++) {
        const float2 hi = *reinterpret_cast<const float2*>(h2 + (size_t)i * 6 + t * 2);
        const float eri = hi.x * ar2[t * 2 + 0] + hi.y * ar2[t * 2 + 1];
        const float a0 = al2[t * 2 + 0], a1 = al2[t * 2 + 1];

        float e[16], v0[16], v1[16];
        float mx = -1e30f;
        #pragma unroll
        for (int j = 0; j < 16; j++) {
            const int s = src[(size_t)t * E + i * 16 + j];
            const float2 p = *reinterpret_cast<const float2*>(h2 + (size_t)s * 6 + t * 2);
            v0[j] = p.x; v1[j] = p.y;
            float ev = p.x * a0 + p.y * a1 + eri;
            ev = ev > 0.f ? ev : 0.2f * ev;
            e[j] = ev;
            mx = fmaxf(mx, ev);
        }
        float sum = 0.f;
        #pragma unroll
        for (int j = 0; j < 16; j++) { e[j] = __expf(e[j] - mx); sum += e[j]; }
        const float inv = 1.0f / sum;
        float o0 = 0.f, o1 = 0.f;
        #pragma unroll
        for (int j = 0; j < 16; j++) { o0 += e[j] * v0[j]; o1 += e[j] * v1[j]; }
        acc0 += o0 * inv + b2[t * 2 + 0];
        acc1 += o1 * inv + b2[t * 2 + 1];
    }
    out[(size_t)i * 2 + 0] = acc0 * (1.0f / 3.0f);
    out[(size_t)i * 2 + 1] = acc1 * (1.0f / 3.0f);
    if (out_size >= 4 * n) {
        out[(size_t)n * 2 + i * 2 + 0] = 1.0f;
        out[(size_t)n * 2 + i * 2 + 1] = 1.0f;
    }
}

// ---------------- launch ----------------
extern "C" void kernel_launch(void* const* d_in, const int* in_sizes, int n_in,
                              void* d_out, int out_size)
{
    const float* feat = (const float*)d_in[0];
    const float* W0   = (const float*)d_in[1];
    const float* al0  = (const float*)d_in[2];
    const float* ar0  = (const float*)d_in[3];
    const float* b0   = (const float*)d_in[4];
    const float* W1   = (const float*)d_in[5];
    const float* al1  = (const float*)d_in[6];
    const float* ar1  = (const float*)d_in[7];
    const float* b1   = (const float*)d_in[8];
    const float* W2   = (const float*)d_in[9];
    const float* al2  = (const float*)d_in[10];
    const float* ar2  = (const float*)d_in[11];
    const float* b2   = (const float*)d_in[12];
    const int*   src  = (const int*)d_in[13];
    float* out = (float*)d_out;

    const int n = in_sizes[0] / 128;   // 30000

    __half *featH, *w0h, *w1h, *h, *x1h, *x2h;
    float *el, *er, *h2;
    cudaGetSymbolAddress((void**)&featH, g_featH);
    cudaGetSymbolAddress((void**)&w0h,   g_w0h);
    cudaGetSymbolAddress((void**)&w1h,   g_w1h);
    cudaGetSymbolAddress((void**)&h,     g_h);
    cudaGetSymbolAddress((void**)&x1h,   g_x1h);
    cudaGetSymbolAddress((void**)&x2h,   g_x2h);
    cudaGetSymbolAddress((void**)&el,    g_el);
    cudaGetSymbolAddress((void**)&er,    g_er);
    cudaGetSymbolAddress((void**)&h2,    g_h2);

    const dim3 ggrid((n + BM - 1) / BM, 6);

    // fused fp16 conversions
    const int nf4 = n * 128 / 4;
    const int nw0 = 3 * 128 * 256 / 4;
    const int nw1 = 3 * 256 * 256 / 4;
    f2h_all<<<(nf4 + nw0 + nw1 + 255) / 256, 256>>>(
        feat, featH, nf4, W0, w0h, nw0, W1, w1h, nw1);

    // layer 0
    hgemm<<<ggrid, 256>>>(featH, w0h, h, n, 128);
    eler_kernel<<<(n * 3 * 32 + 255) / 256, 256>>>(h, al0, ar0, el, er, n);
    agg_kernel<<<n, 128>>>(h, el, er, src, b0, x1h, n);

    // layer 1
    hgemm<<<ggrid, 256>>>(x1h, w1h, h, n, 256);
    eler_kernel<<<(n * 3 * 32 + 255) / 256, 256>>>(h, al1, ar1, el, er, n);
    agg_kernel<<<n, 128>>>(h, el, er, src, b1, x2h, n);

    // layer 2
    gemm2_kernel<<<(n * 32 + 255) / 256, 256>>>(x2h, W2, h2, n);
    final_kernel<<<(n + 127) / 128, 128>>>(h2, al2, ar2, b2, src, out, n, out_size);
}

// round 11
// speedup vs baseline: 1.1895x; 1.1895x over previous
#include <cuda_runtime.h>
#include <cuda_fp16.h>
#include <mma.h>
#include <cstdint>

using namespace nvcuda;

#define NMAX 30000

// ---------------- scratch (no allocation allowed) ----------------
__device__ __half g_featH[NMAX * 128];     // fp16 copy of input feats
__device__ __half g_w0h[3 * 128 * 256];    // fp16 W0
__device__ __half g_w1h[3 * 256 * 256];    // fp16 W1
__device__ __half g_h [NMAX * 768];        // projected feats fp16, [N][t][256]
__device__ __half g_x1h[NMAX * 256];       // layer-0 output (fp16)
__device__ __half g_x2h[NMAX * 256];       // layer-1 output (fp16)
__device__ float  g_el[NMAX * 12];         // [N][t][head]
__device__ float  g_er[NMAX * 12];
__device__ float  g_h2[NMAX * 6];          // layer-2 projected [N][t][2]

// ---------------- fused fp32 -> fp16 conversion (3 segments) ----------------
__global__ __launch_bounds__(256) void f2h_all(
    const float* __restrict__ in0, __half* __restrict__ out0, int n0,
    const float* __restrict__ in1, __half* __restrict__ out1, int n1,
    const float* __restrict__ in2, __half* __restrict__ out2, int n2)
{
    int i = blockIdx.x * blockDim.x + threadIdx.x;   // float4 index
    const float* in; __half* out;
    if (i < n0)            { in = in0; out = out0; }
    else if ((i -= n0) < n1) { in = in1; out = out1; }
    else if ((i -= n1) < n2) { in = in2; out = out2; }
    else return;
    float4 v = reinterpret_cast<const float4*>(in)[i];
    __half2 a = __floats2half2_rn(v.x, v.y);
    __half2 b = __floats2half2_rn(v.z, v.w);
    reinterpret_cast<__half2*>(out)[2 * i + 0] = a;
    reinterpret_cast<__half2*>(out)[2 * i + 1] = b;
}

// ---------------- HMMA GEMM + fused el/er -----------------------------------
// C_fp16[N,768] = X_fp16[N,K] @ {W_t_fp16[K,256]}; each CTA's 128-col tile is
// exactly 2 heads (64 cols each) of etype t, so el/er dots are computed in the
// epilogue from fp32 accumulators and written directly.
#define BM 128
#define BN 128
#define BKH 32
#define APAD 16
#define BPAD 16

__global__ __launch_bounds__(256, 2) void hgemm(
    const __half* __restrict__ X, const __half* __restrict__ W,
    __half* __restrict__ C,
    const float* __restrict__ al, const float* __restrict__ ar,
    float* __restrict__ el, float* __restrict__ er,
    int M, int K)
{
    __shared__ __half As[BM][BKH + APAD];
    __shared__ __half Bs[BKH][BN + BPAD];

    const int tid  = threadIdx.x;
    const int wid  = tid >> 5;
    const int lane = tid & 31;
    const int row0 = blockIdx.x * BM;
    const int ct   = blockIdx.y;
    const int t    = ct >> 1;
    const int colbase = (ct & 1) * 128;
    const __half* Wt = W + (size_t)t * K * 256;

    const int wm = wid >> 1;
    const int wn = wid & 1;
    const int head = (ct & 1) * 2 + wn;           // head within etype (0..3)

    wmma::fragment<wmma::accumulator, 16, 16, 16, float> acc[2][4];
    #pragma unroll
    for (int i = 0; i < 2; i++)
        #pragma unroll
        for (int j = 0; j < 4; j++) wmma::fill_fragment(acc[i][j], 0.0f);

    const int ar_ = tid >> 1;
    const int as_ = (tid & 1) * 16;
    const int br_ = tid >> 3;
    const int bs_ = (tid & 7) * 16;

    for (int k0 = 0; k0 < K; k0 += BKH) {
        uint4 v0 = make_uint4(0u, 0u, 0u, 0u), v1 = v0;
        if (row0 + ar_ < M) {
            const __half* xp = X + (size_t)(row0 + ar_) * K + k0 + as_;
            v0 = *reinterpret_cast<const uint4*>(xp);
            v1 = *reinterpret_cast<const uint4*>(xp + 8);
        }
        *reinterpret_cast<uint4*>(&As[ar_][as_])     = v0;
        *reinterpret_cast<uint4*>(&As[ar_][as_ + 8]) = v1;

        const __half* wp = Wt + (size_t)(k0 + br_) * 256 + colbase + bs_;
        *reinterpret_cast<uint4*>(&Bs[br_][bs_])     = *reinterpret_cast<const uint4*>(wp);
        *reinterpret_cast<uint4*>(&Bs[br_][bs_ + 8]) = *reinterpret_cast<const uint4*>(wp + 8);

        __syncthreads();

        #pragma unroll
        for (int kk = 0; kk < BKH; kk += 16) {
            wmma::fragment<wmma::matrix_a, 16, 16, 16, __half, wmma::row_major> af[2];
            wmma::fragment<wmma::matrix_b, 16, 16, 16, __half, wmma::row_major> bf[4];
            #pragma unroll
            for (int i = 0; i < 2; i++)
                wmma::load_matrix_sync(af[i], &As[wm * 32 + i * 16][kk], BKH + APAD);
            #pragma unroll
            for (int j = 0; j < 4; j++)
                wmma::load_matrix_sync(bf[j], &Bs[kk][wn * 64 + j * 16], BN + BPAD);
            #pragma unroll
            for (int i = 0; i < 2; i++)
                #pragma unroll
                for (int j = 0; j < 4; j++)
                    wmma::mma_sync(acc[i][j], af[i], bf[j], acc[i][j]);
        }
        __syncthreads();
    }

    // epilogue: patch -> fp16 store + fused el/er dot products
    float* patch = reinterpret_cast<float*>(&As[0][0]) + wid * 256;
    const int pr = lane >> 1;          // row in patch
    const int pc = (lane & 1) * 8;     // col half (0 or 8)
    const float* alh = al + t * 256 + head * 64;
    const float* arh = ar + t * 256 + head * 64;

    #pragma unroll
    for (int i = 0; i < 2; i++) {
        const int grow = row0 + wm * 32 + i * 16 + pr;
        float elacc = 0.f, eracc = 0.f;
        #pragma unroll
        for (int j = 0; j < 4; j++) {
            wmma::store_matrix_sync(patch, acc[i][j], 16, wmma::mem_row_major);
            __syncwarp();
            float r8[8];
            #pragma unroll
            for (int q = 0; q < 8; q++) r8[q] = patch[pr * 16 + pc + q];
            if (grow < M) {
                __half2 hv[4];
                #pragma unroll
                for (int q = 0; q < 4; q++)
                    hv[q] = __floats2half2_rn(r8[2 * q], r8[2 * q + 1]);
                *reinterpret_cast<uint4*>(
                    C + (size_t)grow * 768 + ct * 128 + wn * 64 + j * 16 + pc) =
                    *reinterpret_cast<uint4*>(hv);
            }
            float4 a0 = *reinterpret_cast<const float4*>(alh + j * 16 + pc);
            float4 a1 = *reinterpret_cast<const float4*>(alh + j * 16 + pc + 4);
            float4 b0 = *reinterpret_cast<const float4*>(arh + j * 16 + pc);
            float4 b1 = *reinterpret_cast<const float4*>(arh + j * 16 + pc + 4);
            elacc += r8[0]*a0.x + r8[1]*a0.y + r8[2]*a0.z + r8[3]*a0.w
                   + r8[4]*a1.x + r8[5]*a1.y + r8[6]*a1.z + r8[7]*a1.w;
            eracc += r8[0]*b0.x + r8[1]*b0.y + r8[2]*b0.z + r8[3]*b0.w
                   + r8[4]*b1.x + r8[5]*b1.y + r8[6]*b1.z + r8[7]*b1.w;
            __syncwarp();
        }
        elacc += __shfl_xor_sync(0xffffffffu, elacc, 1);
        eracc += __shfl_xor_sync(0xffffffffu, eracc, 1);
        if ((lane & 1) == 0 && grow < M) {
            el[(size_t)grow * 12 + t * 4 + head] = elacc;
            er[(size_t)grow * 12 + t * 4 + head] = eracc;
        }
    }
}

// ---------------- aggregation: 2 nodes/block, warp-autonomous ----------------
__global__ __launch_bounds__(192) void agg_kernel(
    const __half* __restrict__ h, const float* __restrict__ el,
    const float* __restrict__ er, const int* __restrict__ src,
    const float* __restrict__ bias, __half* __restrict__ xout,
    int n)
{
    const int tid   = threadIdx.x;
    const int local = tid / 96;          // node slot within block (0/1)
    const int wt    = (tid % 96) / 32;   // etype
    const int lane  = tid & 31;
    const int i     = blockIdx.x * 2 + local;
    const int E     = n * 16;

    __shared__ int   s_src [2][3][16];
    __shared__ float s_alpha[2][3][4][16];   // [node][t][head][j]
    __shared__ float s_part[2][3][256];

    if (i < n) {
        // ---- per-warp alpha: lanes 0-15 own one edge each ----
        int s = 0;
        float a[4] = {0.f, 0.f, 0.f, 0.f};
        if (lane < 16) {
            s = src[(size_t)wt * E + i * 16 + lane];
            s_src[local][wt][lane] = s;
            const float4 el4 = *reinterpret_cast<const float4*>(el + (size_t)s * 12 + wt * 4);
            const float4 er4 = *reinterpret_cast<const float4*>(er + (size_t)i * 12 + wt * 4);
            a[0] = el4.x + er4.x;  a[1] = el4.y + er4.y;
            a[2] = el4.z + er4.z;  a[3] = el4.w + er4.w;
            #pragma unroll
            for (int q = 0; q < 4; q++) a[q] = a[q] > 0.f ? a[q] : 0.2f * a[q];
        }
        // width-16 softmax per head (all 32 lanes execute; high half harmless)
        #pragma unroll
        for (int q = 0; q < 4; q++) {
            float m = a[q];
            #pragma unroll
            for (int o = 1; o < 16; o <<= 1)
                m = fmaxf(m, __shfl_xor_sync(0xffffffffu, m, o, 16));
            float ex = __expf(a[q] - m);
            float sm = ex;
            #pragma unroll
            for (int o = 1; o < 16; o <<= 1)
                sm += __shfl_xor_sync(0xffffffffu, sm, o, 16);
            a[q] = ex / sm;
        }
        if (lane < 16) {
            #pragma unroll
            for (int q = 0; q < 4; q++) s_alpha[local][wt][q][lane] = a[q];
        }
        __syncwarp();

        // ---- gather: lane = col octet (16B loads), head = lane>>3 ----
        const float* ap = s_alpha[local][wt][lane >> 3];
        const __half* hb = h + wt * 256 + lane * 8;
        float acc[8] = {0.f, 0.f, 0.f, 0.f, 0.f, 0.f, 0.f, 0.f};
        #pragma unroll
        for (int j = 0; j < 16; j++) {
            const float aw = ap[j];
            uint4 v = *reinterpret_cast<const uint4*>(
                hb + (size_t)s_src[local][wt][j] * 768);
            const __half2* hv = reinterpret_cast<const __half2*>(&v);
            #pragma unroll
            for (int q = 0; q < 4; q++) {
                float2 f = __half22float2(hv[q]);
                acc[2 * q]     += aw * f.x;
                acc[2 * q + 1] += aw * f.y;
            }
        }
        #pragma unroll
        for (int q = 0; q < 8; q++) s_part[local][wt][lane * 8 + q] = acc[q];
    }
    __syncthreads();

    // ---- combine: 64 threads = 2 nodes x 32 octets ----
    if (tid < 64) {
        const int nl = tid >> 5, oct = tid & 31;
        const int ii = blockIdx.x * 2 + nl;
        if (ii < n) {
            __half2 hv[4];
            #pragma unroll
            for (int q = 0; q < 4; q++) {
                float r[2];
                #pragma unroll
                for (int u = 0; u < 2; u++) {
                    const int c = oct * 8 + 2 * q + u;
                    float sv = s_part[nl][0][c] + s_part[nl][1][c] + s_part[nl][2][c]
                             + bias[c] + bias[256 + c] + bias[512 + c];
                    sv *= (1.0f / 3.0f);
                    r[u] = sv > 0.f ? sv : (__expf(sv) - 1.0f);
                }
                hv[q] = __floats2half2_rn(r[0], r[1]);
            }
            *reinterpret_cast<uint4*>(xout + (size_t)ii * 256 + oct * 8) =
                *reinterpret_cast<uint4*>(hv);
        }
    }
}

// ---------------- layer-2 projection: warp per row, vectorized -------------
__global__ __launch_bounds__(256) void gemm2_kernel(
    const __half* __restrict__ X, const float* __restrict__ W2,
    float* __restrict__ h2, int n)
{
    const int w    = (blockIdx.x * blockDim.x + threadIdx.x) >> 5;
    const int lane = threadIdx.x & 31;
    if (w >= n) return;

    uint4 v = *reinterpret_cast<const uint4*>(X + (size_t)w * 256 + lane * 8);
    const __half2* hv = reinterpret_cast<const __half2*>(&v);

    float s[6] = {0.f, 0.f, 0.f, 0.f, 0.f, 0.f};
    #pragma unroll
    for (int q = 0; q < 4; q++) {
        float2 f = __half22float2(hv[q]);
        const int d = lane * 8 + 2 * q;
        #pragma unroll
        for (int t = 0; t < 3; t++) {
            s[t * 2 + 0] += f.x * W2[t * 512 + d * 2 + 0] + f.y * W2[t * 512 + (d + 1) * 2 + 0];
            s[t * 2 + 1] += f.x * W2[t * 512 + d * 2 + 1] + f.y * W2[t * 512 + (d + 1) * 2 + 1];
        }
    }
    #pragma unroll
    for (int o = 16; o > 0; o >>= 1)
        #pragma unroll
        for (int q = 0; q < 6; q++)
            s[q] += __shfl_xor_sync(0xffffffffu, s[q], o);
    if (lane < 6) h2[(size_t)w * 6 + lane] = s[lane];
}

// ---------------- final: layer-2 attention + outputs ----------------
__global__ __launch_bounds__(128) void final_kernel(
    const float* __restrict__ h2, const float* __restrict__ al2,
    const float* __restrict__ ar2, const float* __restrict__ b2,
    const int* __restrict__ src, float* __restrict__ out,
    int n, int out_size)
{
    const int i = blockIdx.x * blockDim.x + threadIdx.x;
    if (i >= n) return;
    const int E = n * 16;

    float acc0 = 0.f, acc1 = 0.f;
    for (int t = 0; t < 3; t++) {
        const float2 hi = *reinterpret_cast<const float2*>(h2 + (size_t)i * 6 + t * 2);
        const float eri = hi.x * ar2[t * 2 + 0] + hi.y * ar2[t * 2 + 1];
        const float a0 = al2[t * 2 + 0], a1 = al2[t * 2 + 1];

        float e[16], v0[16], v1[16];
        float mx = -1e30f;
        #pragma unroll
        for (int j = 0; j < 16; j++) {
            const int s = src[(size_t)t * E + i * 16 + j];
            const float2 p = *reinterpret_cast<const float2*>(h2 + (size_t)s * 6 + t * 2);
            v0[j] = p.x; v1[j] = p.y;
            float ev = p.x * a0 + p.y * a1 + eri;
            ev = ev > 0.f ? ev : 0.2f * ev;
            e[j] = ev;
            mx = fmaxf(mx, ev);
        }
        float sum = 0.f;
        #pragma unroll
        for (int j = 0; j < 16; j++) { e[j] = __expf(e[j] - mx); sum += e[j]; }
        const float inv = 1.0f / sum;
        float o0 = 0.f, o1 = 0.f;
        #pragma unroll
        for (int j = 0; j < 16; j++) { o0 += e[j] * v0[j]; o1 += e[j] * v1[j]; }
        acc0 += o0 * inv + b2[t * 2 + 0];
        acc1 += o1 * inv + b2[t * 2 + 1];
    }
    out[(size_t)i * 2 + 0] = acc0 * (1.0f / 3.0f);
    out[(size_t)i * 2 + 1] = acc1 * (1.0f / 3.0f);
    if (out_size >= 4 * n) {
        out[(size_t)n * 2 + i * 2 + 0] = 1.0f;
        out[(size_t)n * 2 + i * 2 + 1] = 1.0f;
    }
}

// ---------------- launch ----------------
extern "C" void kernel_launch(void* const* d_in, const int* in_sizes, int n_in,
                              void* d_out, int out_size)
{
    const float* feat = (const float*)d_in[0];
    const float* W0   = (const float*)d_in[1];
    const float* al0  = (const float*)d_in[2];
    const float* ar0  = (const float*)d_in[3];
    const float* b0   = (const float*)d_in[4];
    const float* W1   = (const float*)d_in[5];
    const float* al1  = (const float*)d_in[6];
    const float* ar1  = (const float*)d_in[7];
    const float* b1   = (const float*)d_in[8];
    const float* W2   = (const float*)d_in[9];
    const float* al2  = (const float*)d_in[10];
    const float* ar2  = (const float*)d_in[11];
    const float* b2   = (const float*)d_in[12];
    const int*   src  = (const int*)d_in[13];
    float* out = (float*)d_out;

    const int n = in_sizes[0] / 128;   // 30000

    __half *featH, *w0h, *w1h, *h, *x1h, *x2h;
    float *el, *er, *h2;
    cudaGetSymbolAddress((void**)&featH, g_featH);
    cudaGetSymbolAddress((void**)&w0h,   g_w0h);
    cudaGetSymbolAddress((void**)&w1h,   g_w1h);
    cudaGetSymbolAddress((void**)&h,     g_h);
    cudaGetSymbolAddress((void**)&x1h,   g_x1h);
    cudaGetSymbolAddress((void**)&x2h,   g_x2h);
    cudaGetSymbolAddress((void**)&el,    g_el);
    cudaGetSymbolAddress((void**)&er,    g_er);
    cudaGetSymbolAddress((void**)&h2,    g_h2);

    const dim3 ggrid((n + BM - 1) / BM, 6);

    // fused fp16 conversions
    const int nf4 = n * 128 / 4;
    const int nw0 = 3 * 128 * 256 / 4;
    const int nw1 = 3 * 256 * 256 / 4;
    f2h_all<<<(nf4 + nw0 + nw1 + 255) / 256, 256>>>(
        feat, featH, nf4, W0, w0h, nw0, W1, w1h, nw1);

    // layer 0 (hgemm writes h + el + er)
    hgemm<<<ggrid, 256>>>(featH, w0h, h, al0, ar0, el, er, n, 128);
    agg_kernel<<<(n + 1) / 2, 192>>>(h, el, er, src, b0, x1h, n);

    // layer 1
    hgemm<<<ggrid, 256>>>(x1h, w1h, h, al1, ar1, el, er, n, 256);
    agg_kernel<<<(n + 1) / 2, 192>>>(h, el, er, src, b1, x2h, n);

    // layer 2
    gemm2_kernel<<<(n * 32 + 255) / 256, 256>>>(x2h, W2, h2, n);
    final_kernel<<<(n + 127) / 128, 128>>>(h2, al2, ar2, b2, src, out, n, out_size);
}